// round 16
// baseline (speedup 1.0000x reference)
#include <cuda_runtime.h>
#include <cuda_fp16.h>
#include <math.h>
#include <stddef.h>
#include <stdint.h>

// MLA shapes (compile-time constants)
#define B_    2
#define S_    2048
#define H_    2048
#define NH_   16
#define QL_   1536
#define KVL_  512
#define NOPE_ 128
#define ROPE_ 64
#define VD_   128
#define QKH_  192
#define ROWS_ (B_*S_)   // 4096

// ---------------- scratch (device globals: no allocs allowed) ----------------
__device__ float g_qa  [(size_t)ROWS_*QL_];
__device__ float g_q   [(size_t)ROWS_*NH_*QKH_];
__device__ float g_kvf [(size_t)ROWS_*(KVL_+ROPE_)];
__device__ float g_kvn [(size_t)ROWS_*KVL_];
__device__ float g_kpe [(size_t)ROWS_*ROPE_];
__device__ float g_kvab[(size_t)B_*NH_*S_*256];
__device__ float g_att [(size_t)ROWS_*NH_*VD_];
__device__ float g_cos [(size_t)S_*ROPE_];
__device__ float g_sin [(size_t)S_*ROPE_];

// ---------------- fp16 helpers ----------------
// pack two floats into half2 bits (lo = a, hi = b), round-to-nearest
__device__ __forceinline__ uint32_t f2h2(float a, float b) {
    __half2 h = __floats2half2_rn(a, b);
    return *reinterpret_cast<uint32_t*>(&h);
}

// fp16 MMA, fp32 accumulate: m16n8k16
#define MMA_F16(d, a0, a1, a2, a3, b0, b1)                                   \
    asm volatile(                                                            \
        "mma.sync.aligned.m16n8k16.row.col.f32.f16.f16.f32 "                 \
        "{%0,%1,%2,%3}, {%4,%5,%6,%7}, {%8,%9}, {%0,%1,%2,%3};"              \
        : "+f"((d)[0]), "+f"((d)[1]), "+f"((d)[2]), "+f"((d)[3])             \
        : "r"(a0), "r"(a1), "r"(a2), "r"(a3), "r"(b0), "r"(b1))

// ---------------- tensor-core GEMM: C = A(MxK) @ W(NxK)^T + bias ------------
// fp16 mma m16n8k16, fp32 accumulate. 128x128 tile, BK=32, 256 threads,
// 8 warps 2x4 (warp tile 64x32, 4x4 m16n8 tiles, 2 k16-steps per tile).
// Single-buffered half smem, stride 72 halves (36 words == 4 mod 32):
// fragment half2 loads hit banks 4g+tg -> all 32 distinct, conflict-free.
__global__ void __launch_bounds__(256, 2) sgemm_bias(
    const float* __restrict__ A, const float* __restrict__ W,
    const float* __restrict__ bias, float* __restrict__ C,
    int M, int N, int K,
    int zdA, long long sA, int zmB, long long sB, long long sC)
{
    __shared__ __align__(16) __half As[128][72];
    __shared__ __align__(16) __half Bs[128][72];

    const int z = blockIdx.z;
    A += (long long)(z / zdA) * sA;
    W += (long long)(z % zmB) * sB;
    C += (long long)z * sC;

    const int tid  = threadIdx.x;
    const int warp = tid >> 5, lane = tid & 31;
    const int wm = warp >> 2;
    const int wn = warp & 3;
    const int g  = lane >> 2;
    const int tg = lane & 3;
    const int m0 = blockIdx.y * 128;
    const int n0 = blockIdx.x * 128;

    float acc[4][4][4];
#pragma unroll
    for (int mt = 0; mt < 4; mt++)
#pragma unroll
        for (int nt = 0; nt < 4; nt++)
#pragma unroll
            for (int r = 0; r < 4; r++) acc[mt][nt][r] = 0.f;

    for (int k0 = 0; k0 < K; k0 += 32) {
#pragma unroll
        for (int it = 0; it < 4; it++) {
            int idx = tid + it * 256;
            int r = idx >> 3;
            int c = (idx & 7) << 2;
            float4 va = *reinterpret_cast<const float4*>(A + (size_t)(m0 + r) * K + k0 + c);
            uint2 pa; pa.x = f2h2(va.x, va.y); pa.y = f2h2(va.z, va.w);
            *reinterpret_cast<uint2*>(&As[r][c]) = pa;
            int n = n0 + r;
            uint2 pb = make_uint2(0u, 0u);
            if (n < N) {
                float4 vb = *reinterpret_cast<const float4*>(W + (size_t)n * K + k0 + c);
                pb.x = f2h2(vb.x, vb.y); pb.y = f2h2(vb.z, vb.w);
            }
            *reinterpret_cast<uint2*>(&Bs[r][c]) = pb;
        }
        __syncthreads();

#pragma unroll
        for (int ks = 0; ks < 2; ks++) {
            const int kc = ks * 16 + 2 * tg;
            uint32_t af[4][4], bf[4][2];
#pragma unroll
            for (int mt = 0; mt < 4; mt++) {
                int rb = wm * 64 + mt * 16 + g;
                af[mt][0] = *reinterpret_cast<const uint32_t*>(&As[rb][kc]);
                af[mt][1] = *reinterpret_cast<const uint32_t*>(&As[rb + 8][kc]);
                af[mt][2] = *reinterpret_cast<const uint32_t*>(&As[rb][kc + 8]);
                af[mt][3] = *reinterpret_cast<const uint32_t*>(&As[rb + 8][kc + 8]);
            }
#pragma unroll
            for (int nt = 0; nt < 4; nt++) {
                int nb = wn * 32 + nt * 8 + g;
                bf[nt][0] = *reinterpret_cast<const uint32_t*>(&Bs[nb][kc]);
                bf[nt][1] = *reinterpret_cast<const uint32_t*>(&Bs[nb][kc + 8]);
            }
#pragma unroll
            for (int mt = 0; mt < 4; mt++)
#pragma unroll
                for (int nt = 0; nt < 4; nt++)
                    MMA_F16(acc[mt][nt], af[mt][0], af[mt][1], af[mt][2], af[mt][3],
                            bf[nt][0], bf[nt][1]);
        }
        __syncthreads();
    }

#pragma unroll
    for (int mt = 0; mt < 4; mt++) {
        int row = m0 + wm * 64 + mt * 16 + g;
#pragma unroll
        for (int nt = 0; nt < 4; nt++) {
            int col = n0 + wn * 32 + nt * 8 + (tg << 1);
            if (col < N) {
                float2 bv = make_float2(0.f, 0.f);
                if (bias) bv = *reinterpret_cast<const float2*>(bias + col);
                float2 v0 = make_float2(acc[mt][nt][0] + bv.x, acc[mt][nt][1] + bv.y);
                float2 v1 = make_float2(acc[mt][nt][2] + bv.x, acc[mt][nt][3] + bv.y);
                *reinterpret_cast<float2*>(C + (size_t)row * N + col) = v0;
                *reinterpret_cast<float2*>(C + (size_t)(row + 8) * N + col) = v1;
            }
        }
    }
}

// ---------------- RMSNorm (in-place), one block per row --------------------
__global__ void __launch_bounds__(256) rmsnorm_k(float* __restrict__ x,
                                                 const float* __restrict__ w, int D)
{
    const int row = blockIdx.x;
    float* xr = x + (size_t)row * D;
    float ss = 0.f;
    for (int i = threadIdx.x; i < D; i += 256) { float v = xr[i]; ss = fmaf(v, v, ss); }
    __shared__ float red[8];
#pragma unroll
    for (int d = 16; d; d >>= 1) ss += __shfl_xor_sync(0xffffffffu, ss, d);
    if ((threadIdx.x & 31) == 0) red[threadIdx.x >> 5] = ss;
    __syncthreads();
    if (threadIdx.x == 0) {
        float t = 0.f;
#pragma unroll
        for (int i = 0; i < 8; i++) t += red[i];
        red[0] = t;
    }
    __syncthreads();
    const float r = rsqrtf(red[0] / (float)D + 1e-6f);
    for (int i = threadIdx.x; i < D; i += 256) xr[i] = w[i] * (xr[i] * r);
}

// ---------------- RoPE tables (fp64 trig for range safety) ------------------
__global__ void rope_tab_k(float* __restrict__ ct, float* __restrict__ st)
{
    const int pos = blockIdx.x;
    const int j = threadIdx.x;
    double inv = pow(10000.0, -((double)j) / 32.0);
    float ang = (float)pos * (float)inv;
    float c = (float)cos((double)ang);
    float s = (float)sin((double)ang);
    ct[pos * 64 + j] = c; ct[pos * 64 + j + 32] = c;
    st[pos * 64 + j] = s; st[pos * 64 + j + 32] = s;
}

// ---------------- kv split: rmsnorm first 512, rope last 64 -----------------
__global__ void __launch_bounds__(256) kvprep_k(
    const float* __restrict__ kvf, const float* __restrict__ w,
    float* __restrict__ kvn, float* __restrict__ kpe,
    const float* __restrict__ ct, const float* __restrict__ st)
{
    const int row = blockIdx.x;
    const float* xr = kvf + (size_t)row * 576;
    float ss = 0.f;
    for (int i = threadIdx.x; i < 512; i += 256) { float v = xr[i]; ss = fmaf(v, v, ss); }
    __shared__ float red[8];
#pragma unroll
    for (int d = 16; d; d >>= 1) ss += __shfl_xor_sync(0xffffffffu, ss, d);
    if ((threadIdx.x & 31) == 0) red[threadIdx.x >> 5] = ss;
    __syncthreads();
    if (threadIdx.x == 0) {
        float t = 0.f;
#pragma unroll
        for (int i = 0; i < 8; i++) t += red[i];
        red[0] = t;
    }
    __syncthreads();
    const float r = rsqrtf(red[0] / 512.f + 1e-6f);
    for (int i = threadIdx.x; i < 512; i += 256)
        kvn[(size_t)row * 512 + i] = w[i] * (xr[i] * r);

    if (threadIdx.x < 32) {
        const int j = threadIdx.x;
        const int pos = row & (S_ - 1);
        float c = ct[pos * 64 + j], s = st[pos * 64 + j];
        float x1 = xr[512 + j], x2 = xr[544 + j];
        kpe[(size_t)row * 64 + j]      = x1 * c - x2 * s;
        kpe[(size_t)row * 64 + 32 + j] = x2 * c + x1 * s;
    }
}

// ---------------- rope on q_pe slice of each head (in-place) ----------------
__global__ void __launch_bounds__(256) ropeq_k(float* __restrict__ q,
                                               const float* __restrict__ ct,
                                               const float* __restrict__ st)
{
    const int idx = blockIdx.x * 256 + threadIdx.x;
    const int row = idx >> 9;
    const int h = (idx >> 5) & 15;
    const int j = idx & 31;
    const int pos = row & (S_ - 1);
    float* p = q + (size_t)row * 3072 + h * 192 + 128;
    float c = ct[pos * 64 + j], s = st[pos * 64 + j];
    float x1 = p[j], x2 = p[j + 32];
    p[j]      = x1 * c - x2 * s;
    p[j + 32] = x2 * c + x1 * s;
}

// ---------------- flash attention (absorbed MLA), 128-row q-tiles, fp16 MMA -
// Warp-row-ownership: 8 warps x 16 full rows. QK warp tile 16x64 over 192-dim
// (12 k16-steps x 8 MMAs); PV 16x128 over 64-dim (4 k16-steps x 16 MMAs).
// Half smem strides 200 / 72 (100 / 36 words == 4 mod 32): fragment half2
// loads conflict-free. Softmax quad-shuffle local; sP warp-private.
__global__ void __launch_bounds__(256) attn_k(
    const float* __restrict__ Q,    // [4096, 3072]
    const float* __restrict__ KV,   // [32][2048][256]: k_abs | v_abs
    const float* __restrict__ Kpe,  // [4096, 64]
    const int*   __restrict__ msk,  // [2, 2048]
    float* __restrict__ Out)        // [4096, 2048]
{
    const int qb = blockIdx.x, h = blockIdx.y, b = blockIdx.z;
    const int tid = threadIdx.x;
    const int warp = tid >> 5, lane = tid & 31;
    const int g = lane >> 2, tg = lane & 3;
    const int w16 = warp * 16;

    extern __shared__ __half smh[];
    __half* sQ  = smh;                 // [128][200] fp16
    __half* sK  = sQ + 128 * 200;      // [64][200]  (k_abs 0..127 | kpe 128..191)
    __half* sVT = sK + 64 * 200;       // [128][72]  (V transposed: [vcol][seq])
    __half* sP  = sVT + 128 * 72;      // [128][72]  (warp-private rows)

    const int s0 = qb * 128;
    const float* Qb = Q + (size_t)(b * 2048 + s0) * 3072 + h * 192;
    for (int idx = tid; idx < 128 * 48; idx += 256) {
        int r = idx / 48, c4 = idx % 48;
        float4 v = *reinterpret_cast<const float4*>(Qb + (size_t)r * 3072 + c4 * 4);
        uint2 p; p.x = f2h2(v.x, v.y); p.y = f2h2(v.z, v.w);
        *reinterpret_cast<uint2*>(&sQ[r * 200 + c4 * 4]) = p;
    }

    const float scale = 0.07216878364870322f;  // 1/sqrt(192)
    const int r1 = w16 + g, r2 = r1 + 8;       // the two rows this thread owns
    const int sg1 = s0 + r1, sg2 = s0 + r2;

    float m1 = -3.0e38f, m2 = -3.0e38f, l1 = 0.f, l2 = 0.f;
    float o[16][4];
#pragma unroll
    for (int nt = 0; nt < 16; nt++)
#pragma unroll
        for (int r = 0; r < 4; r++) o[nt][r] = 0.f;

    const int* mrow = msk + (size_t)b * 2048;
    const int nkt = 2 * qb + 2;

    for (int kt = 0; kt < nkt; kt++) {
        __syncthreads();   // also covers Q staging on the first iteration
        const float* KVb = KV + ((size_t)(b * 16 + h) * 2048 + kt * 64) * 256;
        for (int idx = tid; idx < 64 * 64; idx += 256) {
            int r = idx >> 6, c4 = idx & 63;
            float4 v = *reinterpret_cast<const float4*>(KVb + (size_t)r * 256 + c4 * 4);
            if (c4 < 32) {
                uint2 p; p.x = f2h2(v.x, v.y); p.y = f2h2(v.z, v.w);
                *reinterpret_cast<uint2*>(&sK[r * 200 + c4 * 4]) = p;
            } else {
                int vc = (c4 - 32) * 4;
                sVT[(vc + 0) * 72 + r] = __float2half_rn(v.x);
                sVT[(vc + 1) * 72 + r] = __float2half_rn(v.y);
                sVT[(vc + 2) * 72 + r] = __float2half_rn(v.z);
                sVT[(vc + 3) * 72 + r] = __float2half_rn(v.w);
            }
        }
        const float* Kpb = Kpe + (size_t)(b * 2048 + kt * 64) * 64;
        for (int idx = tid; idx < 64 * 16; idx += 256) {
            int r = idx >> 4, c4 = idx & 15;
            float4 v = *reinterpret_cast<const float4*>(Kpb + (size_t)r * 64 + c4 * 4);
            uint2 p; p.x = f2h2(v.x, v.y); p.y = f2h2(v.z, v.w);
            *reinterpret_cast<uint2*>(&sK[r * 200 + 128 + c4 * 4]) = p;
        }
        __syncthreads();

        // ---- scores: 16x64 per warp over 192-dim contraction (12 k16) ----
        float sc[8][4];
#pragma unroll
        for (int nt = 0; nt < 8; nt++)
#pragma unroll
            for (int r = 0; r < 4; r++) sc[nt][r] = 0.f;

#pragma unroll
        for (int ks = 0; ks < 12; ks++) {
            const int kc = ks * 16 + 2 * tg;
            uint32_t a0 = *reinterpret_cast<const uint32_t*>(&sQ[r1 * 200 + kc]);
            uint32_t a1 = *reinterpret_cast<const uint32_t*>(&sQ[r2 * 200 + kc]);
            uint32_t a2 = *reinterpret_cast<const uint32_t*>(&sQ[r1 * 200 + kc + 8]);
            uint32_t a3 = *reinterpret_cast<const uint32_t*>(&sQ[r2 * 200 + kc + 8]);
#pragma unroll
            for (int nt = 0; nt < 8; nt++) {
                const __half* bk = &sK[(nt * 8 + g) * 200 + kc];
                uint32_t b0 = *reinterpret_cast<const uint32_t*>(bk);
                uint32_t b1 = *reinterpret_cast<const uint32_t*>(bk + 8);
                MMA_F16(sc[nt], a0, a1, a2, a3, b0, b1);
            }
        }

        // ---- scale + mask + row max (warp-local) ----
        const bool diag = (kt >= 2 * qb);
        float tm1 = -3.0e38f, tm2 = -3.0e38f;
#pragma unroll
        for (int nt = 0; nt < 8; nt++) {
            int t0 = kt * 64 + nt * 8 + 2 * tg, t1 = t0 + 1;
            int mv0 = mrow[t0], mv1 = mrow[t1];
            float v0 = sc[nt][0] * scale; if ((diag && t0 > sg1) || mv0 == 0) v0 = -1e15f;
            float v1 = sc[nt][1] * scale; if ((diag && t1 > sg1) || mv1 == 0) v1 = -1e15f;
            float v2 = sc[nt][2] * scale; if ((diag && t0 > sg2) || mv0 == 0) v2 = -1e15f;
            float v3 = sc[nt][3] * scale; if ((diag && t1 > sg2) || mv1 == 0) v3 = -1e15f;
            sc[nt][0] = v0; sc[nt][1] = v1; sc[nt][2] = v2; sc[nt][3] = v3;
            tm1 = fmaxf(tm1, fmaxf(v0, v1));
            tm2 = fmaxf(tm2, fmaxf(v2, v3));
        }
        tm1 = fmaxf(tm1, __shfl_xor_sync(0xffffffffu, tm1, 1));
        tm1 = fmaxf(tm1, __shfl_xor_sync(0xffffffffu, tm1, 2));
        tm2 = fmaxf(tm2, __shfl_xor_sync(0xffffffffu, tm2, 1));
        tm2 = fmaxf(tm2, __shfl_xor_sync(0xffffffffu, tm2, 2));

        float nm1 = fmaxf(m1, tm1), nm2 = fmaxf(m2, tm2);
        float al1 = expf(m1 - nm1), al2 = expf(m2 - nm2);
        m1 = nm1; m2 = nm2;

        // ---- exp + P store (fp16 half2, warp-private rows) + row sum ----
        float ls1 = 0.f, ls2 = 0.f;
#pragma unroll
        for (int nt = 0; nt < 8; nt++) {
            float p0 = expf(sc[nt][0] - nm1);
            float p1 = expf(sc[nt][1] - nm1);
            float p2 = expf(sc[nt][2] - nm2);
            float p3 = expf(sc[nt][3] - nm2);
            ls1 += p0 + p1; ls2 += p2 + p3;
            int jc = nt * 8 + 2 * tg;
            *reinterpret_cast<uint32_t*>(&sP[r1 * 72 + jc]) = f2h2(p0, p1);
            *reinterpret_cast<uint32_t*>(&sP[r2 * 72 + jc]) = f2h2(p2, p3);
        }
        ls1 += __shfl_xor_sync(0xffffffffu, ls1, 1);
        ls1 += __shfl_xor_sync(0xffffffffu, ls1, 2);
        ls2 += __shfl_xor_sync(0xffffffffu, ls2, 1);
        ls2 += __shfl_xor_sync(0xffffffffu, ls2, 2);
        l1 = l1 * al1 + ls1;
        l2 = l2 * al2 + ls2;
        __syncwarp();

        // ---- O rescale + PV: 16x128 per warp over 64-dim (4 k16) ----
#pragma unroll
        for (int nt = 0; nt < 16; nt++) {
            o[nt][0] *= al1; o[nt][1] *= al1; o[nt][2] *= al2; o[nt][3] *= al2;
        }
#pragma unroll
        for (int ks = 0; ks < 4; ks++) {
            const int kc = ks * 16 + 2 * tg;
            uint32_t a0 = *reinterpret_cast<const uint32_t*>(&sP[r1 * 72 + kc]);
            uint32_t a1 = *reinterpret_cast<const uint32_t*>(&sP[r2 * 72 + kc]);
            uint32_t a2 = *reinterpret_cast<const uint32_t*>(&sP[r1 * 72 + kc + 8]);
            uint32_t a3 = *reinterpret_cast<const uint32_t*>(&sP[r2 * 72 + kc + 8]);
#pragma unroll
            for (int nt = 0; nt < 16; nt++) {
                const __half* bv = &sVT[(nt * 8 + g) * 72 + kc];
                uint32_t b0 = *reinterpret_cast<const uint32_t*>(bv);
                uint32_t b1 = *reinterpret_cast<const uint32_t*>(bv + 8);
                MMA_F16(o[nt], a0, a1, a2, a3, b0, b1);
            }
        }
    }

    // ---- epilogue ----
    const float i1 = 1.f / l1, i2 = 1.f / l2;
    float* orow1 = Out + (size_t)(b * 2048 + sg1) * 2048 + h * 128;
    float* orow2 = Out + (size_t)(b * 2048 + sg2) * 2048 + h * 128;
#pragma unroll
    for (int nt = 0; nt < 16; nt++) {
        int c = nt * 8 + 2 * tg;
        *reinterpret_cast<float2*>(orow1 + c) = make_float2(o[nt][0] * i1, o[nt][1] * i1);
        *reinterpret_cast<float2*>(orow2 + c) = make_float2(o[nt][2] * i2, o[nt][3] * i2);
    }
}

// ------------------------------- host side ---------------------------------
extern "C" void kernel_launch(void* const* d_in, const int* in_sizes, int n_in,
                              void* d_out, int out_size)
{
    (void)in_sizes; (void)n_in; (void)out_size;
    const float* x        = (const float*)d_in[0];
    const int*   mask     = (const int*)  d_in[1];
    const float* wq_a_w   = (const float*)d_in[2];
    const float* wq_a_b   = (const float*)d_in[3];
    const float* q_norm_w = (const float*)d_in[4];
    const float* wq_b_w   = (const float*)d_in[5];
    const float* wq_b_b   = (const float*)d_in[6];
    const float* wkv_a_w  = (const float*)d_in[7];
    const float* wkv_a_b  = (const float*)d_in[8];
    const float* kv_norm_w= (const float*)d_in[9];
    const float* wkv_b_w  = (const float*)d_in[10];
    const float* wo_w     = (const float*)d_in[11];
    const float* wo_b     = (const float*)d_in[12];
    float* out = (float*)d_out;

    float *qa, *q, *kvf, *kvn, *kpe, *kvab, *att, *ct, *st;
    cudaGetSymbolAddress((void**)&qa,   g_qa);
    cudaGetSymbolAddress((void**)&q,    g_q);
    cudaGetSymbolAddress((void**)&kvf,  g_kvf);
    cudaGetSymbolAddress((void**)&kvn,  g_kvn);
    cudaGetSymbolAddress((void**)&kpe,  g_kpe);
    cudaGetSymbolAddress((void**)&kvab, g_kvab);
    cudaGetSymbolAddress((void**)&att,  g_att);
    cudaGetSymbolAddress((void**)&ct,   g_cos);
    cudaGetSymbolAddress((void**)&st,   g_sin);

    rope_tab_k<<<S_, 32>>>(ct, st);

    // q_a = x @ wq_a^T + b   [4096,2048]x[1536,2048]
    { dim3 g(QL_ / 128, ROWS_ / 128, 1);
      sgemm_bias<<<g, 256>>>(x, wq_a_w, wq_a_b, qa, ROWS_, QL_, H_, 1, 0, 1, 0, 0); }
    rmsnorm_k<<<ROWS_, 256>>>(qa, q_norm_w, QL_);
    // q = q_a @ wq_b^T + b   [4096,1536]x[3072,1536]
    { dim3 g((NH_ * QKH_) / 128, ROWS_ / 128, 1);
      sgemm_bias<<<g, 256>>>(qa, wq_b_w, wq_b_b, q, ROWS_, NH_ * QKH_, QL_, 1, 0, 1, 0, 0); }
    // kv_full = x @ wkv_a^T + b   [4096,2048]x[576,2048]
    { dim3 g((KVL_ + ROPE_ + 127) / 128, ROWS_ / 128, 1);
      sgemm_bias<<<g, 256>>>(x, wkv_a_w, wkv_a_b, kvf, ROWS_, KVL_ + ROPE_, H_, 1, 0, 1, 0, 0); }
    kvprep_k<<<ROWS_, 256>>>(kvf, kv_norm_w, kvn, kpe, ct, st);
    ropeq_k<<<(ROWS_ * NH_ * 32) / 256, 256>>>(q, ct, st);

    // absorbed K/V: per (b,h): kvab[z] = kvn[b] (2048x512) @ wkv_b[h] (256x512)^T
    { dim3 g(256 / 128, S_ / 128, B_ * NH_);
      sgemm_bias<<<g, 256>>>(kvn, wkv_b_w, nullptr, kvab, S_, 256, KVL_,
                             NH_, (long long)S_ * KVL_,
                             NH_, 256LL * KVL_,
                             (long long)S_ * 256); }

    // flash attention (fp16 tensor-core, 128-row q-tiles, warp-row-ownership)
    // smem halves: sQ 128*200 + sK 64*200 + sVT 128*72 + sP 128*72 = 56,832
    // -> 56,832 * 2 B = 113,664 B (re-derived from device layout)
    const int attn_smem = (128 * 200 + 64 * 200 + 128 * 72 + 128 * 72) * 2;
    cudaFuncSetAttribute(attn_k, cudaFuncAttributeMaxDynamicSharedMemorySize, attn_smem);
    attn_k<<<dim3(S_ / 128, NH_, B_), 256, attn_smem>>>(q, kvab, kpe, mask, att);

    // out = att @ wo^T + b   [4096,2048]x[2048,2048]
    { dim3 g(H_ / 128, ROWS_ / 128, 1);
      sgemm_bias<<<g, 256>>>(att, wo_w, wo_b, out, ROWS_, H_, NH_ * VD_, 1, 0, 1, 0, 0); }
}